// round 11
// baseline (speedup 1.0000x reference)
#include <cuda_runtime.h>
#include <cuda_fp16.h>

#define IN_DIM   32768
#define OUT_DIM  32768
#define BATCH    2048
#define RPB      2            // batch rows per block (half2-interleaved in smem)
#define NTHREADS 1024
#define COL_SEGS (OUT_DIM / 4 / NTHREADS)   // 8
#define SMEM_BYTES (IN_DIM * 4)             // one half2 plane: rows 0,1 interleaved

// Packed metadata, SoA (12 B / column total):
//   g_pidx[j] : ia | ib<<16
//   g_pcx[j]  : (c0, ca) as half2 bits
//   g_pcy[j]  : (cb, cab) as half2 bits
// SoA keeps every per-seg LDG.128 fully coalesced (4 wavefronts, no stride waste).
__device__ unsigned g_pidx[OUT_DIM];
__device__ unsigned g_pcx[OUT_DIM];
__device__ unsigned g_pcy[OUT_DIM];

__constant__ float GC[16][4] = {
    {0.f,0.f,0.f,0.f}, {0.f,0.f,0.f,1.f}, {0.f,1.f,0.f,-1.f}, {0.f,1.f,0.f,0.f},
    {0.f,0.f,1.f,-1.f}, {0.f,0.f,1.f,0.f}, {0.f,1.f,1.f,-2.f}, {0.f,1.f,1.f,-1.f},
    {1.f,-1.f,-1.f,1.f}, {1.f,-1.f,-1.f,2.f}, {1.f,0.f,-1.f,0.f}, {1.f,0.f,-1.f,1.f},
    {1.f,-1.f,0.f,0.f}, {1.f,-1.f,0.f,1.f}, {1.f,0.f,0.f,-1.f}, {1.f,0.f,0.f,0.f}
};

// prep: softmax coeffs -> fp16 pack, idx pair -> 16+16 bit pack.
// idx dtype detected per-block from the first 512 32-bit words of idx_a:
// little-endian int64 < 32768 -> all odd words zero; int32 random -> not.
__global__ void prep_kernel(const float* __restrict__ w,
                            const void* __restrict__ pa,
                            const void* __restrict__ pb) {
    const unsigned* wa = (const unsigned*)pa;
    int is64 = !__syncthreads_or(wa[2 * threadIdx.x + 1] != 0u);

    int j = blockIdx.x * blockDim.x + threadIdx.x;
    if (j >= OUT_DIM) return;

    float wv[16];
    const float4* w4 = reinterpret_cast<const float4*>(w) + (size_t)j * 4;
#pragma unroll
    for (int q = 0; q < 4; q++) {
        float4 v = w4[q];
        wv[4*q+0] = v.x; wv[4*q+1] = v.y; wv[4*q+2] = v.z; wv[4*q+3] = v.w;
    }
    float m = wv[0];
#pragma unroll
    for (int i = 1; i < 16; i++) m = fmaxf(m, wv[i]);
    float s = 0.f;
#pragma unroll
    for (int i = 0; i < 16; i++) { wv[i] = __expf(wv[i] - m); s += wv[i]; }
    float inv = 1.f / s;

    float c0 = 0.f, ca = 0.f, cb = 0.f, cab = 0.f;
#pragma unroll
    for (int i = 0; i < 16; i++) {
        float p = wv[i];
        c0  = fmaf(p, GC[i][0], c0);
        ca  = fmaf(p, GC[i][1], ca);
        cb  = fmaf(p, GC[i][2], cb);
        cab = fmaf(p, GC[i][3], cab);
    }
    c0 *= inv; ca *= inv; cb *= inv; cab *= inv;

    __half2 h01 = __floats2half2_rn(c0, ca);
    __half2 h23 = __floats2half2_rn(cb, cab);
    g_pcx[j] = *reinterpret_cast<unsigned*>(&h01);
    g_pcy[j] = *reinterpret_cast<unsigned*>(&h23);

    unsigned ia, ib;
    if (is64) {
        ia = (unsigned)reinterpret_cast<const long long*>(pa)[j];
        ib = (unsigned)reinterpret_cast<const long long*>(pb)[j];
    } else {
        ia = (unsigned)reinterpret_cast<const int*>(pa)[j];
        ib = (unsigned)reinterpret_cast<const int*>(pb)[j];
    }
    g_pidx[j] = ia | (ib << 16);
}

extern __shared__ unsigned char smem_raw[];

// One column's contribution for one batch row (3 FMA)
__device__ __forceinline__ float gate3(float a, float b, float2 c01, float2 c23) {
    return fmaf(a, fmaf(c23.y, b, c01.y), fmaf(c23.x, b, c01.x));
}

__global__ void __launch_bounds__(NTHREADS, 1)
logic_main(const float* __restrict__ x, float* __restrict__ out) {
    half2* __restrict__ s01 = reinterpret_cast<half2*>(smem_raw);  // rows 0,1 interleaved

    const uint4* __restrict__ pidx4 = reinterpret_cast<const uint4*>(g_pidx);
    const uint4* __restrict__ pcx4  = reinterpret_cast<const uint4*>(g_pcx);
    const uint4* __restrict__ pcy4  = reinterpret_cast<const uint4*>(g_pcy);

    int r0 = blockIdx.x * RPB;   // BATCH % RPB == 0: no tail
    const int t0 = threadIdx.x;

    // ── Row load first: needs only x (prep may still be running under PDL).
    const float4* x0 = reinterpret_cast<const float4*>(x + (size_t)r0 * IN_DIM);
    const float4* x1 = reinterpret_cast<const float4*>(x + (size_t)(r0 + 1) * IN_DIM);
#pragma unroll 2
    for (int i = threadIdx.x; i < IN_DIM / 4; i += NTHREADS) {
        float4 v0 = __ldcs(&x0[i]);
        float4 v1 = __ldcs(&x1[i]);
        union { half2 h[4]; float4 f; } u;
        u.h[0] = __floats2half2_rn(v0.x, v1.x);
        u.h[1] = __floats2half2_rn(v0.y, v1.y);
        u.h[2] = __floats2half2_rn(v0.z, v1.z);
        u.h[3] = __floats2half2_rn(v0.w, v1.w);
        *reinterpret_cast<float4*>(&s01[4*i]) = u.f;
    }

    // ── PDL: wait for prep's metadata stores to be visible.
    cudaGridDependencySynchronize();

    // ── Metadata pipeline prologue (latency hidden by the barrier below).
    uint4 ii = __ldg(&pidx4[t0]);
    uint4 cx = __ldg(&pcx4[t0]);
    uint4 cy = __ldg(&pcy4[t0]);

    __syncthreads();

    float4* o0 = reinterpret_cast<float4*>(out + (size_t)r0 * OUT_DIM);
    float4* o1 = o0 + OUT_DIM / 4;

    // ── Main loop, depth-1 software pipeline on metadata
    int t = t0;
#pragma unroll
    for (int seg = 0; seg < COL_SEGS; seg++) {
        uint4 n_ii, n_cx, n_cy;
        if (seg + 1 < COL_SEGS) {
            int tn = t + NTHREADS;
            n_ii = __ldg(&pidx4[tn]);
            n_cx = __ldg(&pcx4[tn]);
            n_cy = __ldg(&pcy4[tn]);
        }

        unsigned iw[4] = {ii.x, ii.y, ii.z, ii.w};
        unsigned cxw[4] = {cx.x, cx.y, cx.z, cx.w};
        unsigned cyw[4] = {cy.x, cy.y, cy.z, cy.w};

        float4 r_0, r_1;
        float* p0 = &r_0.x; float* p1 = &r_1.x;
#pragma unroll
        for (int k = 0; k < 4; k++) {
            unsigned ia = iw[k] & 0xFFFFu, ib = iw[k] >> 16;
            half2 a01 = s01[ia], b01 = s01[ib];
            float2 c01 = __half22float2(*reinterpret_cast<__half2*>(&cxw[k])); // c0, ca
            float2 c23 = __half22float2(*reinterpret_cast<__half2*>(&cyw[k])); // cb, cab
            float2 af = __half22float2(a01), bf = __half22float2(b01);
            p0[k] = gate3(af.x, bf.x, c01, c23);
            p1[k] = gate3(af.y, bf.y, c01, c23);
        }

        __stcs(&o0[t], r_0);
        __stcs(&o1[t], r_1);

        ii = n_ii; cx = n_cx; cy = n_cy;
        t += NTHREADS;
    }
}

extern "C" void kernel_launch(void* const* d_in, const int* in_sizes, int n_in,
                              void* d_out, int out_size) {
    const float* x  = (const float*)d_in[0];
    const void*  ia = d_in[1];
    const void*  ib = d_in[2];
    const float* w  = (const float*)d_in[3];
    float* out = (float*)d_out;

    prep_kernel<<<OUT_DIM / 256, 256>>>(w, ia, ib);

    cudaFuncSetAttribute(logic_main, cudaFuncAttributeMaxDynamicSharedMemorySize, SMEM_BYTES);

    // PDL launch: main starts while prep drains; it row-loads, then
    // cudaGridDependencySynchronize() gates the metadata reads.
    cudaLaunchConfig_t cfg = {};
    cfg.gridDim  = dim3(BATCH / RPB);   // 1024 blocks
    cfg.blockDim = dim3(NTHREADS);
    cfg.dynamicSmemBytes = SMEM_BYTES;
    cfg.stream = 0;
    cudaLaunchAttribute attr[1];
    attr[0].id = cudaLaunchAttributeProgrammaticStreamSerialization;
    attr[0].val.programmaticStreamSerializationAllowed = 1;
    cfg.attrs = attr;
    cfg.numAttrs = 1;
    cudaLaunchKernelEx(&cfg, logic_main, x, out);
}

// round 12
// speedup vs baseline: 1.1978x; 1.1978x over previous
#include <cuda_runtime.h>
#include <cuda_fp16.h>

#define IN_DIM   32768
#define OUT_DIM  32768
#define BATCH    2048
#define NPAIRS   (BATCH / 2)      // 1024 tasks (2 rows each)
#define NTHREADS 1024
#define NCOMP    768              // warps 0-23: compute
#define NLOAD    256              // warps 24-31: loaders
#define GRID     148

// Overlapping ping-pong fp16 planes (half2 = rows r0,r1 interleaved, 4 B/col)
//   plane E: bytes [0, 131072)
//   plane O: bytes [98304, 229376)
//   shared window = E grps [6144,8192) = O grps [0,2048)  (grp = 4 columns)
#define O_BASE_B   98304
#define SMEM_BYTES 229376         // 224 KB
#define GRPS       (IN_DIM / 4)   // 8192 float4-groups of columns
#define PRE_GRPS   6144           // prefetched by loader warps during compute
#define TAIL_GRPS  2048           // filled by all threads after the plane dies

// Packed metadata: 12 B / column (idx pair 16+16 bits, 4 coeffs fp16) — AoS, as in R8
__device__ unsigned g_pidx[OUT_DIM];
__device__ uint2    g_pc[OUT_DIM];

__constant__ float GC[16][4] = {
    {0.f,0.f,0.f,0.f}, {0.f,0.f,0.f,1.f}, {0.f,1.f,0.f,-1.f}, {0.f,1.f,0.f,0.f},
    {0.f,0.f,1.f,-1.f}, {0.f,0.f,1.f,0.f}, {0.f,1.f,1.f,-2.f}, {0.f,1.f,1.f,-1.f},
    {1.f,-1.f,-1.f,1.f}, {1.f,-1.f,-1.f,2.f}, {1.f,0.f,-1.f,0.f}, {1.f,0.f,-1.f,1.f},
    {1.f,-1.f,0.f,0.f}, {1.f,-1.f,0.f,1.f}, {1.f,0.f,0.f,-1.f}, {1.f,0.f,0.f,0.f}
};

// prep: softmax coeffs -> fp16 pack, idx pair -> 16+16 bit pack.
// idx dtype detected per-block from the first 512 32-bit words of idx_a:
// little-endian int64 < 32768 -> all odd words zero; int32 random -> not.
__global__ void prep_kernel(const float* __restrict__ w,
                            const void* __restrict__ pa,
                            const void* __restrict__ pb) {
    const unsigned* wa = (const unsigned*)pa;
    int is64 = !__syncthreads_or(wa[2 * threadIdx.x + 1] != 0u);

    int j = blockIdx.x * blockDim.x + threadIdx.x;
    if (j >= OUT_DIM) return;

    float wv[16];
    const float4* w4 = reinterpret_cast<const float4*>(w) + (size_t)j * 4;
#pragma unroll
    for (int q = 0; q < 4; q++) {
        float4 v = w4[q];
        wv[4*q+0] = v.x; wv[4*q+1] = v.y; wv[4*q+2] = v.z; wv[4*q+3] = v.w;
    }
    float m = wv[0];
#pragma unroll
    for (int i = 1; i < 16; i++) m = fmaxf(m, wv[i]);
    float s = 0.f;
#pragma unroll
    for (int i = 0; i < 16; i++) { wv[i] = __expf(wv[i] - m); s += wv[i]; }
    float inv = 1.f / s;

    float c0 = 0.f, ca = 0.f, cb = 0.f, cab = 0.f;
#pragma unroll
    for (int i = 0; i < 16; i++) {
        float p = wv[i];
        c0  = fmaf(p, GC[i][0], c0);
        ca  = fmaf(p, GC[i][1], ca);
        cb  = fmaf(p, GC[i][2], cb);
        cab = fmaf(p, GC[i][3], cab);
    }
    c0 *= inv; ca *= inv; cb *= inv; cab *= inv;

    __half2 h01 = __floats2half2_rn(c0, ca);
    __half2 h23 = __floats2half2_rn(cb, cab);
    uint2 pc;
    pc.x = *reinterpret_cast<unsigned*>(&h01);
    pc.y = *reinterpret_cast<unsigned*>(&h23);
    g_pc[j] = pc;

    unsigned ia, ib;
    if (is64) {
        ia = (unsigned)reinterpret_cast<const long long*>(pa)[j];
        ib = (unsigned)reinterpret_cast<const long long*>(pb)[j];
    } else {
        ia = (unsigned)reinterpret_cast<const int*>(pa)[j];
        ib = (unsigned)reinterpret_cast<const int*>(pb)[j];
    }
    g_pidx[j] = ia | (ib << 16);
}

extern __shared__ unsigned char smem_raw[];

__device__ __forceinline__ float gate3(float a, float b, float2 c01, float2 c23) {
    return fmaf(a, fmaf(c23.y, b, c01.y), fmaf(c23.x, b, c01.x));
}

// Load one float4-group (4 cols) of both rows, pack to 4 half2, store 16 B.
__device__ __forceinline__ void pack_group(const float4* __restrict__ ra,
                                           const float4* __restrict__ rb,
                                           half2* __restrict__ plane,
                                           int grp) {
    float4 va = __ldcs(&ra[grp]);
    float4 vb = __ldcs(&rb[grp]);
    union { half2 h[4]; float4 f; } u;
    u.h[0] = __floats2half2_rn(va.x, vb.x);
    u.h[1] = __floats2half2_rn(va.y, vb.y);
    u.h[2] = __floats2half2_rn(va.z, vb.z);
    u.h[3] = __floats2half2_rn(va.w, vb.w);
    *reinterpret_cast<float4*>(&plane[4 * grp]) = u.f;
}

__global__ void __launch_bounds__(NTHREADS, 1)
logic_main(const float* __restrict__ x, float* __restrict__ out) {
    half2* const planeE = reinterpret_cast<half2*>(smem_raw);
    half2* const planeO = reinterpret_cast<half2*>(smem_raw + O_BASE_B);

    const uint4* __restrict__ pidx4 = reinterpret_cast<const uint4*>(g_pidx);
    const uint4* __restrict__ pc4   = reinterpret_cast<const uint4*>(g_pc);

    const int tid = threadIdx.x;
    int task = blockIdx.x;
    int parity = 0;

    // Prologue: all threads fill plane E with the first task's pair.
    {
        const float4* ra = reinterpret_cast<const float4*>(x + (size_t)(2 * task) * IN_DIM);
        const float4* rb = ra + GRPS;
        for (int g = tid; g < GRPS; g += NTHREADS)
            pack_group(ra, rb, planeE, g);
    }
    __syncthreads();

    for (; task < NPAIRS; task += GRID, parity ^= 1) {
        half2* const cur = parity ? planeO : planeE;
        half2* const nxt = parity ? planeE : planeO;
        const bool hasNext = (task + GRID) < NPAIRS;

        const float4* na = reinterpret_cast<const float4*>(x + (size_t)(2 * (task + GRID)) * IN_DIM);
        const float4* nb = na + GRPS;

        if (tid < NCOMP) {
            // ── Compute warps: R8 loop (depth-1 metadata pipeline), stride NCOMP
            float4* o0 = reinterpret_cast<float4*>(out + (size_t)(2 * task) * OUT_DIM);
            float4* o1 = o0 + OUT_DIM / 4;

            int t = tid;
            uint4 ii  = __ldg(&pidx4[t]);
            uint4 ccA = __ldg(&pc4[2*t]);
            uint4 ccB = __ldg(&pc4[2*t+1]);

            while (t < GRPS) {
                int tn = t + NCOMP;
                uint4 n_ii, n_ccA, n_ccB;
                if (tn < GRPS) {
                    n_ii  = __ldg(&pidx4[tn]);
                    n_ccA = __ldg(&pc4[2*tn]);
                    n_ccB = __ldg(&pc4[2*tn+1]);
                }

                unsigned iw[4] = {ii.x, ii.y, ii.z, ii.w};
                unsigned cw[8] = {ccA.x, ccA.y, ccA.z, ccA.w,
                                  ccB.x, ccB.y, ccB.z, ccB.w};

                float4 r_0, r_1;
                float* p0 = &r_0.x; float* p1 = &r_1.x;
#pragma unroll
                for (int k = 0; k < 4; k++) {
                    unsigned ia = iw[k] & 0xFFFFu, ib = iw[k] >> 16;
                    half2 a01 = cur[ia], b01 = cur[ib];
                    float2 c01 = __half22float2(*reinterpret_cast<__half2*>(&cw[2*k+0]));
                    float2 c23 = __half22float2(*reinterpret_cast<__half2*>(&cw[2*k+1]));
                    float2 af = __half22float2(a01), bf = __half22float2(b01);
                    p0[k] = gate3(af.x, bf.x, c01, c23);
                    p1[k] = gate3(af.y, bf.y, c01, c23);
                }

                __stcs(&o0[t], r_0);
                __stcs(&o1[t], r_1);

                ii = n_ii; ccA = n_ccA; ccB = n_ccB;
                t = tn;
            }
        } else if (hasNext) {
            // ── Loader warps: fill the 6144-group region of nxt disjoint from cur.
            //    parity 0 (computing E): next-O grps [2048, 8192)
            //    parity 1 (computing O): next-E grps [0, 6144)
            const int pre_base = parity ? 0 : TAIL_GRPS;
            const int lid = tid - NCOMP;     // 0..255
#pragma unroll 4
            for (int i = 0; i < PRE_GRPS / NLOAD; i++)   // 24 iterations
                pack_group(na, nb, nxt, pre_base + lid + i * NLOAD);
        }
        __syncthreads();   // cur dead; prefetched region complete

        if (hasNext) {
            // ── Tail fill (shared window), all 1024 threads:
            //    parity 0: next-O grps [0, 2048); parity 1: next-E grps [6144, 8192)
            const int tail_base = parity ? PRE_GRPS : 0;
#pragma unroll
            for (int q = 0; q < TAIL_GRPS / NTHREADS; q++)  // 2 iterations
                pack_group(na, nb, nxt, tail_base + tid + q * NTHREADS);
            __syncthreads();   // next plane fully ready
        }
    }
}

extern "C" void kernel_launch(void* const* d_in, const int* in_sizes, int n_in,
                              void* d_out, int out_size) {
    const float* x  = (const float*)d_in[0];
    const void*  ia = d_in[1];
    const void*  ib = d_in[2];
    const float* w  = (const float*)d_in[3];
    float* out = (float*)d_out;

    prep_kernel<<<OUT_DIM / 256, 256>>>(w, ia, ib);

    cudaFuncSetAttribute(logic_main, cudaFuncAttributeMaxDynamicSharedMemorySize, SMEM_BYTES);
    logic_main<<<GRID, NTHREADS, SMEM_BYTES>>>(x, out);
}

// round 13
// speedup vs baseline: 1.3390x; 1.1180x over previous
#include <cuda_runtime.h>
#include <cuda_fp16.h>

#define IN_DIM   32768
#define OUT_DIM  32768
#define BATCH    2048
#define RPB      2            // batch rows per block (half2-interleaved in smem)
#define NTHREADS 1024
#define COL_SEGS (OUT_DIM / 4 / NTHREADS)   // 8
#define SMEM_BYTES (IN_DIM * 4)             // one half2 plane: rows 0,1 interleaved

// Packed metadata, SoA (12 B / column total):
//   g_pidx[j] : ia | ib<<16
//   g_pcx[j]  : (c0, ca)  as half2 bits
//   g_pcy[j]  : (cb, cab) as half2 bits
// SoA: every per-seg LDG.128 is fully coalesced -> 4 L1 wavefronts per load
// (AoS uint2 coeffs cost 8 wf per load at 32 B warp stride).
__device__ unsigned g_pidx[OUT_DIM];
__device__ unsigned g_pcx[OUT_DIM];
__device__ unsigned g_pcy[OUT_DIM];

__constant__ float GC[16][4] = {
    {0.f,0.f,0.f,0.f}, {0.f,0.f,0.f,1.f}, {0.f,1.f,0.f,-1.f}, {0.f,1.f,0.f,0.f},
    {0.f,0.f,1.f,-1.f}, {0.f,0.f,1.f,0.f}, {0.f,1.f,1.f,-2.f}, {0.f,1.f,1.f,-1.f},
    {1.f,-1.f,-1.f,1.f}, {1.f,-1.f,-1.f,2.f}, {1.f,0.f,-1.f,0.f}, {1.f,0.f,-1.f,1.f},
    {1.f,-1.f,0.f,0.f}, {1.f,-1.f,0.f,1.f}, {1.f,0.f,0.f,-1.f}, {1.f,0.f,0.f,0.f}
};

// prep: softmax coeffs -> fp16 pack, idx pair -> 16+16 bit pack.
// idx dtype detected per-block from the first 512 32-bit words of idx_a:
// little-endian int64 < 32768 -> all odd words zero; int32 random -> not.
__global__ void prep_kernel(const float* __restrict__ w,
                            const void* __restrict__ pa,
                            const void* __restrict__ pb) {
    const unsigned* wa = (const unsigned*)pa;
    int is64 = !__syncthreads_or(wa[2 * threadIdx.x + 1] != 0u);

    int j = blockIdx.x * blockDim.x + threadIdx.x;
    if (j >= OUT_DIM) return;

    float wv[16];
    const float4* w4 = reinterpret_cast<const float4*>(w) + (size_t)j * 4;
#pragma unroll
    for (int q = 0; q < 4; q++) {
        float4 v = w4[q];
        wv[4*q+0] = v.x; wv[4*q+1] = v.y; wv[4*q+2] = v.z; wv[4*q+3] = v.w;
    }
    float m = wv[0];
#pragma unroll
    for (int i = 1; i < 16; i++) m = fmaxf(m, wv[i]);
    float s = 0.f;
#pragma unroll
    for (int i = 0; i < 16; i++) { wv[i] = __expf(wv[i] - m); s += wv[i]; }
    float inv = 1.f / s;

    float c0 = 0.f, ca = 0.f, cb = 0.f, cab = 0.f;
#pragma unroll
    for (int i = 0; i < 16; i++) {
        float p = wv[i];
        c0  = fmaf(p, GC[i][0], c0);
        ca  = fmaf(p, GC[i][1], ca);
        cb  = fmaf(p, GC[i][2], cb);
        cab = fmaf(p, GC[i][3], cab);
    }
    c0 *= inv; ca *= inv; cb *= inv; cab *= inv;

    __half2 h01 = __floats2half2_rn(c0, ca);
    __half2 h23 = __floats2half2_rn(cb, cab);
    g_pcx[j] = *reinterpret_cast<unsigned*>(&h01);
    g_pcy[j] = *reinterpret_cast<unsigned*>(&h23);

    unsigned ia, ib;
    if (is64) {
        ia = (unsigned)reinterpret_cast<const long long*>(pa)[j];
        ib = (unsigned)reinterpret_cast<const long long*>(pb)[j];
    } else {
        ia = (unsigned)reinterpret_cast<const int*>(pa)[j];
        ib = (unsigned)reinterpret_cast<const int*>(pb)[j];
    }
    g_pidx[j] = ia | (ib << 16);
}

extern __shared__ unsigned char smem_raw[];

// One column's contribution for one batch row (3 FMA)
__device__ __forceinline__ float gate3(float a, float b, float2 c01, float2 c23) {
    return fmaf(a, fmaf(c23.y, b, c01.y), fmaf(c23.x, b, c01.x));
}

__global__ void __launch_bounds__(NTHREADS, 1)
logic_main(const float* __restrict__ x, float* __restrict__ out) {
    half2* __restrict__ s01 = reinterpret_cast<half2*>(smem_raw);  // rows 0,1 interleaved

    const uint4* __restrict__ pidx4 = reinterpret_cast<const uint4*>(g_pidx);
    const uint4* __restrict__ pcx4  = reinterpret_cast<const uint4*>(g_pcx);
    const uint4* __restrict__ pcy4  = reinterpret_cast<const uint4*>(g_pcy);

    int r0 = blockIdx.x * RPB;   // BATCH % RPB == 0: no tail
    const int t0 = threadIdx.x;

    // ── Metadata pipeline prologue: seg 0's loads fly during the row-load
    //    phase and the barrier (independent of smem).
    uint4 ii = __ldg(&pidx4[t0]);
    uint4 cx = __ldg(&pcx4[t0]);
    uint4 cy = __ldg(&pcy4[t0]);

    // ── Row load: fp32 rows -> one fp16 half2 plane (streaming, read-once)
    const float4* x0 = reinterpret_cast<const float4*>(x + (size_t)r0 * IN_DIM);
    const float4* x1 = reinterpret_cast<const float4*>(x + (size_t)(r0 + 1) * IN_DIM);
#pragma unroll 2
    for (int i = threadIdx.x; i < IN_DIM / 4; i += NTHREADS) {
        float4 v0 = __ldcs(&x0[i]);
        float4 v1 = __ldcs(&x1[i]);
        union { half2 h[4]; float4 f; } u;
        u.h[0] = __floats2half2_rn(v0.x, v1.x);
        u.h[1] = __floats2half2_rn(v0.y, v1.y);
        u.h[2] = __floats2half2_rn(v0.z, v1.z);
        u.h[3] = __floats2half2_rn(v0.w, v1.w);
        *reinterpret_cast<float4*>(&s01[4*i]) = u.f;
    }
    __syncthreads();

    float4* o0 = reinterpret_cast<float4*>(out + (size_t)r0 * OUT_DIM);
    float4* o1 = o0 + OUT_DIM / 4;

    // ── Main loop, depth-1 software pipeline on SoA metadata
    int t = t0;
#pragma unroll
    for (int seg = 0; seg < COL_SEGS; seg++) {
        uint4 n_ii, n_cx, n_cy;
        if (seg + 1 < COL_SEGS) {
            int tn = t + NTHREADS;
            n_ii = __ldg(&pidx4[tn]);
            n_cx = __ldg(&pcx4[tn]);
            n_cy = __ldg(&pcy4[tn]);
        }

        unsigned iw[4]  = {ii.x, ii.y, ii.z, ii.w};
        unsigned cxw[4] = {cx.x, cx.y, cx.z, cx.w};
        unsigned cyw[4] = {cy.x, cy.y, cy.z, cy.w};

        float4 r_0, r_1;
        float* p0 = &r_0.x; float* p1 = &r_1.x;
#pragma unroll
        for (int k = 0; k < 4; k++) {
            unsigned ia = iw[k] & 0xFFFFu, ib = iw[k] >> 16;
            half2 a01 = s01[ia], b01 = s01[ib];
            float2 c01 = __half22float2(*reinterpret_cast<__half2*>(&cxw[k])); // c0, ca
            float2 c23 = __half22float2(*reinterpret_cast<__half2*>(&cyw[k])); // cb, cab
            float2 af = __half22float2(a01), bf = __half22float2(b01);
            p0[k] = gate3(af.x, bf.x, c01, c23);
            p1[k] = gate3(af.y, bf.y, c01, c23);
        }

        __stcs(&o0[t], r_0);
        __stcs(&o1[t], r_1);

        ii = n_ii; cx = n_cx; cy = n_cy;
        t += NTHREADS;
    }
}

extern "C" void kernel_launch(void* const* d_in, const int* in_sizes, int n_in,
                              void* d_out, int out_size) {
    const float* x  = (const float*)d_in[0];
    const void*  ia = d_in[1];
    const void*  ib = d_in[2];
    const float* w  = (const float*)d_in[3];
    float* out = (float*)d_out;

    prep_kernel<<<OUT_DIM / 256, 256>>>(w, ia, ib);

    cudaFuncSetAttribute(logic_main, cudaFuncAttributeMaxDynamicSharedMemorySize, SMEM_BYTES);
    int grid = BATCH / RPB;   // 1024 blocks
    logic_main<<<grid, NTHREADS, SMEM_BYTES>>>(x, out);
}